// round 6
// baseline (speedup 1.0000x reference)
#include <cuda_runtime.h>
#include <math.h>
#include <stdint.h>

// ---------------- problem constants ----------------
#define B_   2
#define L_   1024
#define DM   1024
#define DS   16
#define DFF  4096
#define DI   2048
#define DTR  64
#define BL   (B_*L_)          // 2048 rows (tokens)
#define XPN  (DTR + 2*DS)     // 96

// ---------------- scratch (device globals; no allocation allowed) ----------------
__device__ float g_xz  [BL * 2 * DI];   // in_proj output (x | z)
__device__ float g_xc  [BL * DI];       // conv+silu(x)
__device__ float g_xdbl[BL * XPN];      // x_proj output (dt|B|C)
__device__ float g_dt  [BL * DI];       // softplus(dt @ dt_proj^T + b)
__device__ float g_y   [BL * DI];       // gated scan output
__device__ float g_mam [BL * DM];       // out_proj output
__device__ float g_zm  [BL * DM];       // Z_mam (post first rmsnorm)
__device__ float g_h   [BL * DFF];      // MLP hidden
__device__ float g_mlp [BL * DM];       // MLP output

#define MMA_TF32(d0,d1,d2,d3,a0,a1,a2,a3,b0,b1)                               \
    asm volatile(                                                             \
        "mma.sync.aligned.m16n8k8.row.col.f32.tf32.tf32.f32 "                 \
        "{%0,%1,%2,%3},{%4,%5,%6,%7},{%8,%9},{%0,%1,%2,%3};"                  \
        : "+f"(d0), "+f"(d1), "+f"(d2), "+f"(d3)                              \
        : "r"(a0), "r"(a1), "r"(a2), "r"(a3), "r"(b0), "r"(b1))

#define CP_ASYNC16(dst, src)                                                   \
    asm volatile("cp.async.cg.shared.global [%0], [%1], 16;" :: "r"(dst), "l"(src))
#define CP_ASYNC16_Z(dst, src, sz)                                             \
    asm volatile("cp.async.cg.shared.global [%0], [%1], 16, %2;" :: "r"(dst), "l"(src), "r"(sz))

// smem: 2 stages x (A[128][36] + B[128][36]) floats
#define TILE_F   (128 * 36)
#define GEMM_SMEM_BYTES (2 * 2 * TILE_F * 4)

// ---------------- TF32 tensor-core GEMM, cp.async double-buffered ----------------
// C[M,N] = A[M,K] @ B[N,K]^T (+bias, +activation)
// ACT: 0 = none, 1 = softplus, 2 = exact gelu
// Block tile 128x128, K-tile 32, 256 threads = 8 warps (2m x 4n), warp tile 64x32.
// Fragment loads are float4 (LDS.128): the k-dimension is consumed in a
// permuted order (k-step ks takes each thread's elements 2ks and 2ks+1 of its
// private 8-float k-run at column 8*t). Since A and B use the same
// permutation per MMA k-lane, the contraction is unchanged.
// Contract: M % 128 == 0, K % 32 == 0, lda/ldb multiples of 4. N may be ragged.
template<int ACT>
__global__ void __launch_bounds__(256, 2)
tc_gemm_nt(const float* __restrict__ A, int lda,
           const float* __restrict__ Bm, int ldb,
           float* __restrict__ C, int ldc,
           int N, int K,
           const float* __restrict__ bias)
{
    extern __shared__ float sm[];
    float* const AsS[2] = { sm,          sm + 2 * TILE_F };
    float* const BsS[2] = { sm + TILE_F, sm + 3 * TILE_F };

    const int tid  = threadIdx.x;
    const int m0   = blockIdx.y * 128;
    const int n0   = blockIdx.x * 128;

    const int warp = tid >> 5;
    const int lane = tid & 31;
    const int wm   = (warp & 1) * 64;     // warp m-offset in block
    const int wn   = (warp >> 1) * 32;    // warp n-offset in block
    const int g    = lane >> 2;           // 0..7
    const int t    = lane & 3;            // 0..3

    // per-thread copy coordinates (4 chunks of 16B per array per stage)
    const int crow = tid >> 3;            // 0..31  (+32 per chunk)
    const int ckc  = (tid & 7) << 2;      // 0,4,...,28

    float acc[4][4][4];
#pragma unroll
    for (int i = 0; i < 4; i++)
#pragma unroll
        for (int j = 0; j < 4; j++)
#pragma unroll
            for (int c = 0; c < 4; c++) acc[i][j][c] = 0.f;

    const int nIt = K >> 5;

    auto load_tile = [&](int stage, int k0) {
        float* as = AsS[stage];
        float* bs = BsS[stage];
#pragma unroll
        for (int i = 0; i < 4; i++) {
            int row = crow + i * 32;
            uint32_t da = (uint32_t)__cvta_generic_to_shared(as + row * 36 + ckc);
            const float* ga = A + (size_t)(m0 + row) * lda + k0 + ckc;
            CP_ASYNC16(da, ga);

            int brow = n0 + row;
            uint32_t db = (uint32_t)__cvta_generic_to_shared(bs + row * 36 + ckc);
            const float* gb = Bm + (size_t)(brow < N ? brow : 0) * ldb + k0 + ckc;
            int sz = (brow < N) ? 16 : 0;
            CP_ASYNC16_Z(db, gb, sz);
        }
        asm volatile("cp.async.commit_group;");
    };

    load_tile(0, 0);

    for (int it = 0; it < nIt; ++it) {
        const int stage = it & 1;
        if (it + 1 < nIt) {
            load_tile((it + 1) & 1, (it + 1) << 5);
            asm volatile("cp.async.wait_group 1;");
        } else {
            asm volatile("cp.async.wait_group 0;");
        }
        __syncthreads();

        const float* as = AsS[stage];
        const float* bs = BsS[stage];
        const int    kcol = 8 * t;        // this thread's private k-run

        // two halves of the 32-k tile; each half = one float4 per row = 2 k-steps
#pragma unroll
        for (int h = 0; h < 2; h++) {
            float4 aq[4][2];
#pragma unroll
            for (int mf = 0; mf < 4; mf++) {
                const float* pa = as + (wm + mf * 16 + g) * 36 + kcol + 4 * h;
                aq[mf][0] = *(const float4*)pa;
                aq[mf][1] = *(const float4*)(pa + 8 * 36);
            }
            float4 bq[4];
#pragma unroll
            for (int nf = 0; nf < 4; nf++)
                bq[nf] = *(const float4*)(bs + (wn + nf * 8 + g) * 36 + kcol + 4 * h);

            // sub-step 0: elements (.x, .y)
#pragma unroll
            for (int mf = 0; mf < 4; mf++)
#pragma unroll
                for (int nf = 0; nf < 4; nf++)
                    MMA_TF32(acc[mf][nf][0], acc[mf][nf][1],
                             acc[mf][nf][2], acc[mf][nf][3],
                             __float_as_uint(aq[mf][0].x), __float_as_uint(aq[mf][1].x),
                             __float_as_uint(aq[mf][0].y), __float_as_uint(aq[mf][1].y),
                             __float_as_uint(bq[nf].x),    __float_as_uint(bq[nf].y));
            // sub-step 1: elements (.z, .w)
#pragma unroll
            for (int mf = 0; mf < 4; mf++)
#pragma unroll
                for (int nf = 0; nf < 4; nf++)
                    MMA_TF32(acc[mf][nf][0], acc[mf][nf][1],
                             acc[mf][nf][2], acc[mf][nf][3],
                             __float_as_uint(aq[mf][0].z), __float_as_uint(aq[mf][1].z),
                             __float_as_uint(aq[mf][0].w), __float_as_uint(aq[mf][1].w),
                             __float_as_uint(bq[nf].z),    __float_as_uint(bq[nf].w));
        }
        __syncthreads();
    }

    // ---- epilogue ----
#pragma unroll
    for (int nf = 0; nf < 4; nf++) {
        int col = n0 + wn + nf * 8 + t * 2;
        if (col >= N) continue;
        float bv0 = bias ? bias[col]     : 0.f;
        float bv1 = bias ? bias[col + 1] : 0.f;
#pragma unroll
        for (int mf = 0; mf < 4; mf++) {
            int row = m0 + wm + mf * 16 + g;
#pragma unroll
            for (int half = 0; half < 2; half++) {
                int r = row + half * 8;
                float v0 = acc[mf][nf][half * 2 + 0] + bv0;
                float v1 = acc[mf][nf][half * 2 + 1] + bv1;
                if (ACT == 1) {
                    v0 = fmaxf(v0, 0.f) + log1pf(expf(-fabsf(v0)));
                    v1 = fmaxf(v1, 0.f) + log1pf(expf(-fabsf(v1)));
                } else if (ACT == 2) {
                    v0 = 0.5f * v0 * (1.f + erff(v0 * 0.70710678118654752f));
                    v1 = 0.5f * v1 * (1.f + erff(v1 * 0.70710678118654752f));
                }
                *(float2*)(C + (size_t)r * ldc + col) = make_float2(v0, v1);
            }
        }
    }
}

// ---------------- causal depthwise conv (K=4) + bias + SiLU ----------------
__global__ void conv_silu_kernel(const float* __restrict__ conv_w,
                                 const float* __restrict__ conv_b)
{
    int idx = blockIdx.x * blockDim.x + threadIdx.x;
    if (idx >= BL * DI) return;
    int d  = idx % DI;
    int bl = idx / DI;
    int l  = bl % L_;

    float acc = conv_b[d];
#pragma unroll
    for (int j = 0; j < 4; j++) {
        int ls = l - 3 + j;
        if (ls >= 0)
            acc += g_xz[(size_t)(bl - (3 - j)) * (2 * DI) + d] * conv_w[d * 4 + j];
    }
    g_xc[idx] = acc / (1.f + __expf(-acc));     // silu
}

// ---------------- selective scan ----------------
__global__ void scan_kernel(const float* __restrict__ A_log,
                            const float* __restrict__ Dp)
{
    const int tid = threadIdx.x;
    const int s   = tid & 15;
    const int cg  = blockIdx.x * 16 + (tid >> 4);   // 0..B_*DI-1
    const int b   = cg / DI;
    const int d   = cg % DI;

    const float a  = -expf(A_log[d * DS + s]);
    const float Dd = Dp[d];

    float h = 0.f;
    for (int l = 0; l < L_; l++) {
        const int bl = b * L_ + l;
        const float dtv = g_dt  [(size_t)bl * DI + d];
        const float xv  = g_xc  [(size_t)bl * DI + d];
        const float Bv  = g_xdbl[bl * XPN + DTR + s];
        const float Cv  = g_xdbl[bl * XPN + DTR + DS + s];

        h = expf(dtv * a) * h + dtv * Bv * xv;

        float p = h * Cv;
        p += __shfl_xor_sync(0xffffffffu, p, 8);
        p += __shfl_xor_sync(0xffffffffu, p, 4);
        p += __shfl_xor_sync(0xffffffffu, p, 2);
        p += __shfl_xor_sync(0xffffffffu, p, 1);

        if (s == 0) {
            float zv = g_xz[(size_t)bl * (2 * DI) + DI + d];
            float yv = p + xv * Dd;
            g_y[(size_t)bl * DI + d] = yv * (zv / (1.f + __expf(-zv)));
        }
    }
}

// ---------------- fused residual add + RMSNorm ----------------
__global__ void rmsnorm_kernel(const float* __restrict__ x,
                               const float* __restrict__ res,
                               const float* __restrict__ w,
                               float* __restrict__ out)
{
    const int row = blockIdx.x;
    const int tid = threadIdx.x;

    float4 xv = ((const float4*)(x   + (size_t)row * DM))[tid];
    float4 rv = ((const float4*)(res + (size_t)row * DM))[tid];
    float v0 = xv.x + rv.x, v1 = xv.y + rv.y, v2 = xv.z + rv.z, v3 = xv.w + rv.w;

    float ss = v0 * v0 + v1 * v1 + v2 * v2 + v3 * v3;
#pragma unroll
    for (int m = 16; m; m >>= 1) ss += __shfl_xor_sync(0xffffffffu, ss, m);

    __shared__ float red[8];
    if ((tid & 31) == 0) red[tid >> 5] = ss;
    __syncthreads();
    if (tid < 8) {
        float tt = red[tid];
#pragma unroll
        for (int m = 4; m; m >>= 1) tt += __shfl_xor_sync(0xffu, tt, m);
        if (tid == 0) red[0] = tt;
    }
    __syncthreads();

    const float scale = rsqrtf(red[0] / (float)DM + 1e-6f);
    float4 wv = ((const float4*)w)[tid];
    float4 o;
    o.x = v0 * scale * wv.x; o.y = v1 * scale * wv.y;
    o.z = v2 * scale * wv.z; o.w = v3 * scale * wv.w;
    ((float4*)(out + (size_t)row * DM))[tid] = o;
}

// ---------------- launch ----------------
extern "C" void kernel_launch(void* const* d_in, const int* in_sizes, int n_in,
                              void* d_out, int out_size)
{
    const float* Z       = (const float*)d_in[0];
    const float* in_w    = (const float*)d_in[1];   // (2*DI, DM)
    const float* conv_w  = (const float*)d_in[2];   // (DI, 4)
    const float* conv_b  = (const float*)d_in[3];   // (DI,)
    const float* xproj_w = (const float*)d_in[4];   // (96, DI)
    const float* dtp_w   = (const float*)d_in[5];   // (DI, 64)
    const float* dtp_b   = (const float*)d_in[6];   // (DI,)
    const float* A_log   = (const float*)d_in[7];   // (DI, DS)
    const float* Dp      = (const float*)d_in[8];   // (DI,)
    const float* outp_w  = (const float*)d_in[9];   // (DM, DI)
    const float* w1      = (const float*)d_in[10];  // (DFF, DM)
    const float* b1      = (const float*)d_in[11];
    const float* w2      = (const float*)d_in[12];  // (DM, DFF)
    const float* b2      = (const float*)d_in[13];
    const float* nw      = (const float*)d_in[14];  // (DM,)
    float* out = (float*)d_out;

    float *xz, *xc, *xdbl, *dtb, *yb, *mam, *zm, *hb, *mlp;
    cudaGetSymbolAddress((void**)&xz,   g_xz);
    cudaGetSymbolAddress((void**)&xc,   g_xc);
    cudaGetSymbolAddress((void**)&xdbl, g_xdbl);
    cudaGetSymbolAddress((void**)&dtb,  g_dt);
    cudaGetSymbolAddress((void**)&yb,   g_y);
    cudaGetSymbolAddress((void**)&mam,  g_mam);
    cudaGetSymbolAddress((void**)&zm,   g_zm);
    cudaGetSymbolAddress((void**)&hb,   g_h);
    cudaGetSymbolAddress((void**)&mlp,  g_mlp);

    cudaFuncSetAttribute(tc_gemm_nt<0>, cudaFuncAttributeMaxDynamicSharedMemorySize, GEMM_SMEM_BYTES);
    cudaFuncSetAttribute(tc_gemm_nt<1>, cudaFuncAttributeMaxDynamicSharedMemorySize, GEMM_SMEM_BYTES);
    cudaFuncSetAttribute(tc_gemm_nt<2>, cudaFuncAttributeMaxDynamicSharedMemorySize, GEMM_SMEM_BYTES);

    const dim3 thr(256);
    const int  SB = GEMM_SMEM_BYTES;

    // 1) xz = Z @ in_proj_w^T            (2048 x 4096, K=1024)
    tc_gemm_nt<0><<<dim3(4096 / 128, BL / 128), thr, SB>>>(Z, DM, in_w, DM, xz, 2 * DI, 2 * DI, DM, nullptr);

    // 2) x = silu(causal_dwconv(x) + b)
    conv_silu_kernel<<<(BL * DI + 255) / 256, thr>>>(conv_w, conv_b);

    // 3) x_dbl = x @ x_proj_w^T          (2048 x 96, K=2048)
    tc_gemm_nt<0><<<dim3(1, BL / 128), thr, SB>>>(xc, DI, xproj_w, DI, xdbl, XPN, XPN, DI, nullptr);

    // 4) dt = softplus(dt_part @ dt_proj_w^T + dt_b)   (2048 x 2048, K=64; A lda=96)
    tc_gemm_nt<1><<<dim3(DI / 128, BL / 128), thr, SB>>>(xdbl, XPN, dtp_w, DTR, dtb, DI, DI, DTR, dtp_b);

    // 5) selective scan (fused gating)
    scan_kernel<<<(B_ * DI) / 16, thr>>>(A_log, Dp);

    // 6) mamba_out = y @ out_proj_w^T    (2048 x 1024, K=2048)
    tc_gemm_nt<0><<<dim3(DM / 128, BL / 128), thr, SB>>>(yb, DI, outp_w, DI, mam, DM, DM, DI, nullptr);

    // 7) Z_mam = rmsnorm(mamba_out + Z)
    rmsnorm_kernel<<<BL, thr>>>(mam, Z, nw, zm);

    // 8) h = gelu(Z_mam @ w1^T + b1)     (2048 x 4096, K=1024)
    tc_gemm_nt<2><<<dim3(DFF / 128, BL / 128), thr, SB>>>(zm, DM, w1, DM, hb, DFF, DFF, DM, b1);

    // 9) mlp = h @ w2^T + b2             (2048 x 1024, K=4096)
    tc_gemm_nt<0><<<dim3(DM / 128, BL / 128), thr, SB>>>(hb, DFF, w2, DFF, mlp, DM, DM, DFF, b2);

    // 10) out = rmsnorm(mlp + Z_mam)
    rmsnorm_kernel<<<BL, thr>>>(mlp, zm, nw, out);
}

// round 8
// speedup vs baseline: 1.7328x; 1.7328x over previous
#include <cuda_runtime.h>
#include <math.h>
#include <stdint.h>

// ---------------- problem constants ----------------
#define B_   2
#define L_   1024
#define DM   1024
#define DS   16
#define DFF  4096
#define DI   2048
#define DTR  64
#define BL   (B_*L_)          // 2048 rows (tokens)
#define XPN  (DTR + 2*DS)     // 96

// ---------------- scratch (device globals; no allocation allowed) ----------------
__device__ float g_xz  [BL * 2 * DI];   // in_proj output (x | z)
__device__ float g_xc  [BL * DI];       // conv+silu(x)
__device__ float g_xdbl[BL * XPN];      // x_proj output (dt|B|C)
__device__ float g_dt  [BL * DI];       // softplus(dt @ dt_proj^T + b)
__device__ float g_y   [BL * DI];       // gated scan output
__device__ float g_mam [BL * DM];       // out_proj output
__device__ float g_zm  [BL * DM];       // Z_mam (post first rmsnorm)
__device__ float g_h   [BL * DFF];      // MLP hidden
__device__ float g_mlp [BL * DM];       // MLP output

#define MMA_TF32(d0,d1,d2,d3,a0,a1,a2,a3,b0,b1)                               \
    asm volatile(                                                             \
        "mma.sync.aligned.m16n8k8.row.col.f32.tf32.tf32.f32 "                 \
        "{%0,%1,%2,%3},{%4,%5,%6,%7},{%8,%9},{%0,%1,%2,%3};"                  \
        : "+f"(d0), "+f"(d1), "+f"(d2), "+f"(d3)                              \
        : "r"(a0), "r"(a1), "r"(a2), "r"(a3), "r"(b0), "r"(b1))

#define CP_ASYNC16(dst, src)                                                   \
    asm volatile("cp.async.cg.shared.global [%0], [%1], 16;" :: "r"(dst), "l"(src))
#define CP_ASYNC16_Z(dst, src, sz)                                             \
    asm volatile("cp.async.cg.shared.global [%0], [%1], 16, %2;" :: "r"(dst), "l"(src), "r"(sz))

// smem: 3 stages x (A[128][36] + B[128][36]) floats
#define TILE_F   (128 * 36)
#define GEMM_SMEM_BYTES (3 * 2 * TILE_F * 4)   // 110592

// ---------------- TF32 tensor-core GEMM, cp.async 3-stage pipeline ----------------
// C[M,N] = A[M,K] @ B[N,K]^T (+bias, +activation)
// ACT: 0 = none, 1 = softplus, 2 = exact gelu
// Block tile 128x128, K-tile 32, 256 threads = 8 warps (2m x 4n), warp tile 64x32.
// Contract: M % 128 == 0, K % 64 == 0 (nIt >= 2), lda/ldb multiples of 4. N ragged OK.
template<int ACT>
__global__ void __launch_bounds__(256, 2)
tc_gemm_nt(const float* __restrict__ A, int lda,
           const float* __restrict__ Bm, int ldb,
           float* __restrict__ C, int ldc,
           int N, int K,
           const float* __restrict__ bias)
{
    extern __shared__ float sm[];
    float* const AsS[3] = { sm,              sm + 2 * TILE_F, sm + 4 * TILE_F };
    float* const BsS[3] = { sm + TILE_F,     sm + 3 * TILE_F, sm + 5 * TILE_F };

    const int tid  = threadIdx.x;
    const int m0   = blockIdx.y * 128;
    const int n0   = blockIdx.x * 128;

    const int warp = tid >> 5;
    const int lane = tid & 31;
    const int wm   = (warp & 1) * 64;     // warp m-offset in block
    const int wn   = (warp >> 1) * 32;    // warp n-offset in block
    const int g    = lane >> 2;           // 0..7
    const int t    = lane & 3;            // 0..3

    const int crow = tid >> 3;            // 0..31  (+32 per chunk)
    const int ckc  = (tid & 7) << 2;      // 0,4,...,28

    float acc[4][4][4];
#pragma unroll
    for (int i = 0; i < 4; i++)
#pragma unroll
        for (int j = 0; j < 4; j++)
#pragma unroll
            for (int c = 0; c < 4; c++) acc[i][j][c] = 0.f;

    const int nIt = K >> 5;

    auto load_tile = [&](int stage, int k0) {
        float* as = AsS[stage];
        float* bs = BsS[stage];
#pragma unroll
        for (int i = 0; i < 4; i++) {
            int row = crow + i * 32;
            uint32_t da = (uint32_t)__cvta_generic_to_shared(as + row * 36 + ckc);
            const float* ga = A + (size_t)(m0 + row) * lda + k0 + ckc;
            CP_ASYNC16(da, ga);

            int brow = n0 + row;
            uint32_t db = (uint32_t)__cvta_generic_to_shared(bs + row * 36 + ckc);
            const float* gb = Bm + (size_t)(brow < N ? brow : 0) * ldb + k0 + ckc;
            int sz = (brow < N) ? 16 : 0;
            CP_ASYNC16_Z(db, gb, sz);
        }
        asm volatile("cp.async.commit_group;");
    };

    // prologue: 2 stages in flight (nIt >= 2 at every call site)
    load_tile(0, 0);
    load_tile(1, 32);

    for (int it = 0; it < nIt; ++it) {
        if (it + 2 < nIt) load_tile((it + 2) % 3, (it + 2) << 5);

        const int rem = nIt - 1 - it;      // pending groups newer than group `it`
        if (rem >= 2)      asm volatile("cp.async.wait_group %0;" :: "n"(2));
        else if (rem == 1) asm volatile("cp.async.wait_group %0;" :: "n"(1));
        else               asm volatile("cp.async.wait_group %0;" :: "n"(0));
        __syncthreads();

        const float* as = AsS[it % 3];
        const float* bs = BsS[it % 3];

#pragma unroll
        for (int ks = 0; ks < 4; ks++) {
            const int kb = ks * 8;

            uint32_t a[4][4];
#pragma unroll
            for (int mf = 0; mf < 4; mf++) {
                int r0 = wm + mf * 16 + g;
                a[mf][0] = __float_as_uint(as[(r0    ) * 36 + kb + t    ]);
                a[mf][1] = __float_as_uint(as[(r0 + 8) * 36 + kb + t    ]);
                a[mf][2] = __float_as_uint(as[(r0    ) * 36 + kb + t + 4]);
                a[mf][3] = __float_as_uint(as[(r0 + 8) * 36 + kb + t + 4]);
            }
            uint32_t b[4][2];
#pragma unroll
            for (int nf = 0; nf < 4; nf++) {
                int c0 = wn + nf * 8 + g;
                b[nf][0] = __float_as_uint(bs[c0 * 36 + kb + t    ]);
                b[nf][1] = __float_as_uint(bs[c0 * 36 + kb + t + 4]);
            }
#pragma unroll
            for (int mf = 0; mf < 4; mf++)
#pragma unroll
                for (int nf = 0; nf < 4; nf++)
                    MMA_TF32(acc[mf][nf][0], acc[mf][nf][1],
                             acc[mf][nf][2], acc[mf][nf][3],
                             a[mf][0], a[mf][1], a[mf][2], a[mf][3],
                             b[nf][0], b[nf][1]);
        }
        __syncthreads();
    }

    // ---- epilogue ----
#pragma unroll
    for (int nf = 0; nf < 4; nf++) {
        int col = n0 + wn + nf * 8 + t * 2;
        if (col >= N) continue;
        float bv0 = bias ? bias[col]     : 0.f;
        float bv1 = bias ? bias[col + 1] : 0.f;
#pragma unroll
        for (int mf = 0; mf < 4; mf++) {
            int row = m0 + wm + mf * 16 + g;
#pragma unroll
            for (int half = 0; half < 2; half++) {
                int r = row + half * 8;
                float v0 = acc[mf][nf][half * 2 + 0] + bv0;
                float v1 = acc[mf][nf][half * 2 + 1] + bv1;
                if (ACT == 1) {
                    v0 = fmaxf(v0, 0.f) + log1pf(expf(-fabsf(v0)));
                    v1 = fmaxf(v1, 0.f) + log1pf(expf(-fabsf(v1)));
                } else if (ACT == 2) {
                    v0 = 0.5f * v0 * (1.f + erff(v0 * 0.70710678118654752f));
                    v1 = 0.5f * v1 * (1.f + erff(v1 * 0.70710678118654752f));
                }
                *(float2*)(C + (size_t)r * ldc + col) = make_float2(v0, v1);
            }
        }
    }
}

// ---------------- causal depthwise conv (K=4) + bias + SiLU ----------------
__global__ void conv_silu_kernel(const float* __restrict__ conv_w,
                                 const float* __restrict__ conv_b)
{
    int idx = blockIdx.x * blockDim.x + threadIdx.x;
    if (idx >= BL * DI) return;
    int d  = idx % DI;
    int bl = idx / DI;
    int l  = bl % L_;

    float acc = conv_b[d];
#pragma unroll
    for (int j = 0; j < 4; j++) {
        int ls = l - 3 + j;
        if (ls >= 0)
            acc += g_xz[(size_t)(bl - (3 - j)) * (2 * DI) + d] * conv_w[d * 4 + j];
    }
    g_xc[idx] = acc / (1.f + __expf(-acc));     // silu
}

// ---------------- selective scan (unroll-8 prefetch) ----------------
// One 16-lane group per channel (b,d); lane s holds state s of DS=16.
// Per 8 steps: 40 independent loads issued up-front (MLP ~40), then the
// serial h-recurrence runs on registers.
__global__ void scan_kernel(const float* __restrict__ A_log,
                            const float* __restrict__ Dp)
{
    const int tid = threadIdx.x;
    const int s   = tid & 15;
    const int cg  = blockIdx.x * 16 + (tid >> 4);   // 0..B_*DI-1
    const int b   = cg / DI;
    const int d   = cg % DI;

    const float a  = -expf(A_log[d * DS + s]);
    const float Dd = Dp[d];

    const float* p_dt = g_dt   + (size_t)b * L_ * DI + d;
    const float* p_x  = g_xc   + (size_t)b * L_ * DI + d;
    const float* p_z  = g_xz   + (size_t)b * L_ * (2 * DI) + DI + d;
    const float* p_B  = g_xdbl + (size_t)b * L_ * XPN + DTR + s;
    const float* p_C  = p_B + DS;
    float*       p_y  = g_y    + (size_t)b * L_ * DI + d;

    float h = 0.f;
    for (int l0 = 0; l0 < L_; l0 += 8) {
        float dtv[8], xv[8], Bv[8], Cv[8], zv[8];
#pragma unroll
        for (int u = 0; u < 8; u++) {
            int l = l0 + u;
            dtv[u] = p_dt[(size_t)l * DI];
            xv[u]  = p_x [(size_t)l * DI];
            zv[u]  = p_z [(size_t)l * 2 * DI];
            Bv[u]  = p_B [l * XPN];
            Cv[u]  = p_C [l * XPN];
        }
#pragma unroll
        for (int u = 0; u < 8; u++) {
            h = __expf(dtv[u] * a) * h + dtv[u] * Bv[u] * xv[u];

            float p = h * Cv[u];
            p += __shfl_xor_sync(0xffffffffu, p, 8);
            p += __shfl_xor_sync(0xffffffffu, p, 4);
            p += __shfl_xor_sync(0xffffffffu, p, 2);
            p += __shfl_xor_sync(0xffffffffu, p, 1);

            if (s == 0) {
                float yv = p + xv[u] * Dd;
                p_y[(size_t)(l0 + u) * DI] = yv * (zv[u] / (1.f + __expf(-zv[u])));
            }
        }
    }
}

// ---------------- fused residual add + RMSNorm ----------------
__global__ void rmsnorm_kernel(const float* __restrict__ x,
                               const float* __restrict__ res,
                               const float* __restrict__ w,
                               float* __restrict__ out)
{
    const int row = blockIdx.x;
    const int tid = threadIdx.x;

    float4 xv = ((const float4*)(x   + (size_t)row * DM))[tid];
    float4 rv = ((const float4*)(res + (size_t)row * DM))[tid];
    float v0 = xv.x + rv.x, v1 = xv.y + rv.y, v2 = xv.z + rv.z, v3 = xv.w + rv.w;

    float ss = v0 * v0 + v1 * v1 + v2 * v2 + v3 * v3;
#pragma unroll
    for (int m = 16; m; m >>= 1) ss += __shfl_xor_sync(0xffffffffu, ss, m);

    __shared__ float red[8];
    if ((tid & 31) == 0) red[tid >> 5] = ss;
    __syncthreads();
    if (tid < 8) {
        float tt = red[tid];
#pragma unroll
        for (int m = 4; m; m >>= 1) tt += __shfl_xor_sync(0xffu, tt, m);
        if (tid == 0) red[0] = tt;
    }
    __syncthreads();

    const float scale = rsqrtf(red[0] / (float)DM + 1e-6f);
    float4 wv = ((const float4*)w)[tid];
    float4 o;
    o.x = v0 * scale * wv.x; o.y = v1 * scale * wv.y;
    o.z = v2 * scale * wv.z; o.w = v3 * scale * wv.w;
    ((float4*)(out + (size_t)row * DM))[tid] = o;
}

// ---------------- launch ----------------
extern "C" void kernel_launch(void* const* d_in, const int* in_sizes, int n_in,
                              void* d_out, int out_size)
{
    const float* Z       = (const float*)d_in[0];
    const float* in_w    = (const float*)d_in[1];   // (2*DI, DM)
    const float* conv_w  = (const float*)d_in[2];   // (DI, 4)
    const float* conv_b  = (const float*)d_in[3];   // (DI,)
    const float* xproj_w = (const float*)d_in[4];   // (96, DI)
    const float* dtp_w   = (const float*)d_in[5];   // (DI, 64)
    const float* dtp_b   = (const float*)d_in[6];   // (DI,)
    const float* A_log   = (const float*)d_in[7];   // (DI, DS)
    const float* Dp      = (const float*)d_in[8];   // (DI,)
    const float* outp_w  = (const float*)d_in[9];   // (DM, DI)
    const float* w1      = (const float*)d_in[10];  // (DFF, DM)
    const float* b1      = (const float*)d_in[11];
    const float* w2      = (const float*)d_in[12];  // (DM, DFF)
    const float* b2      = (const float*)d_in[13];
    const float* nw      = (const float*)d_in[14];  // (DM,)
    float* out = (float*)d_out;

    float *xz, *xc, *xdbl, *dtb, *yb, *mam, *zm, *hb, *mlp;
    cudaGetSymbolAddress((void**)&xz,   g_xz);
    cudaGetSymbolAddress((void**)&xc,   g_xc);
    cudaGetSymbolAddress((void**)&xdbl, g_xdbl);
    cudaGetSymbolAddress((void**)&dtb,  g_dt);
    cudaGetSymbolAddress((void**)&yb,   g_y);
    cudaGetSymbolAddress((void**)&mam,  g_mam);
    cudaGetSymbolAddress((void**)&zm,   g_zm);
    cudaGetSymbolAddress((void**)&hb,   g_h);
    cudaGetSymbolAddress((void**)&mlp,  g_mlp);

    cudaFuncSetAttribute(tc_gemm_nt<0>, cudaFuncAttributeMaxDynamicSharedMemorySize, GEMM_SMEM_BYTES);
    cudaFuncSetAttribute(tc_gemm_nt<1>, cudaFuncAttributeMaxDynamicSharedMemorySize, GEMM_SMEM_BYTES);
    cudaFuncSetAttribute(tc_gemm_nt<2>, cudaFuncAttributeMaxDynamicSharedMemorySize, GEMM_SMEM_BYTES);

    const dim3 thr(256);
    const int  SB = GEMM_SMEM_BYTES;

    // 1) xz = Z @ in_proj_w^T            (2048 x 4096, K=1024)
    tc_gemm_nt<0><<<dim3(4096 / 128, BL / 128), thr, SB>>>(Z, DM, in_w, DM, xz, 2 * DI, 2 * DI, DM, nullptr);

    // 2) x = silu(causal_dwconv(x) + b)
    conv_silu_kernel<<<(BL * DI + 255) / 256, thr>>>(conv_w, conv_b);

    // 3) x_dbl = x @ x_proj_w^T          (2048 x 96, K=2048)
    tc_gemm_nt<0><<<dim3(1, BL / 128), thr, SB>>>(xc, DI, xproj_w, DI, xdbl, XPN, XPN, DI, nullptr);

    // 4) dt = softplus(dt_part @ dt_proj_w^T + dt_b)   (2048 x 2048, K=64; A lda=96)
    tc_gemm_nt<1><<<dim3(DI / 128, BL / 128), thr, SB>>>(xdbl, XPN, dtp_w, DTR, dtb, DI, DI, DTR, dtp_b);

    // 5) selective scan (fused gating)
    scan_kernel<<<(B_ * DI) / 16, thr>>>(A_log, Dp);

    // 6) mamba_out = y @ out_proj_w^T    (2048 x 1024, K=2048)
    tc_gemm_nt<0><<<dim3(DM / 128, BL / 128), thr, SB>>>(yb, DI, outp_w, DI, mam, DM, DM, DI, nullptr);

    // 7) Z_mam = rmsnorm(mamba_out + Z)
    rmsnorm_kernel<<<BL, thr>>>(mam, Z, nw, zm);

    // 8) h = gelu(Z_mam @ w1^T + b1)     (2048 x 4096, K=1024)
    tc_gemm_nt<2><<<dim3(DFF / 128, BL / 128), thr, SB>>>(zm, DM, w1, DM, hb, DFF, DFF, DM, b1);

    // 9) mlp = h @ w2^T + b2             (2048 x 1024, K=4096)
    tc_gemm_nt<0><<<dim3(DM / 128, BL / 128), thr, SB>>>(hb, DFF, w2, DFF, mlp, DM, DM, DFF, b2);

    // 10) out = rmsnorm(mlp + Z_mam)
    rmsnorm_kernel<<<BL, thr>>>(mlp, zm, nw, out);
}

// round 9
// speedup vs baseline: 1.8541x; 1.0700x over previous
#include <cuda_runtime.h>
#include <math.h>
#include <stdint.h>

// ---------------- problem constants ----------------
#define B_   2
#define L_   1024
#define DM   1024
#define DS   16
#define DFF  4096
#define DI   2048
#define DTR  64
#define BL   (B_*L_)          // 2048 rows (tokens)
#define XPN  (DTR + 2*DS)     // 96

// ---------------- scratch (device globals; no allocation allowed) ----------------
__device__ float g_xz  [BL * 2 * DI];   // in_proj output (x | z)
__device__ float g_xc  [BL * DI];       // conv+silu(x)
__device__ float g_xdbl[BL * XPN];      // x_proj output (dt|B|C)
__device__ float g_dt  [BL * DI];       // softplus(dt @ dt_proj^T + b)
__device__ float g_y   [BL * DI];       // gated scan output
__device__ float g_mam [BL * DM];       // out_proj output
__device__ float g_zm  [BL * DM];       // Z_mam (post first rmsnorm)
__device__ float g_h   [BL * DFF];      // MLP hidden
__device__ float g_mlp [BL * DM];       // MLP output

#define MMA_TF32(d0,d1,d2,d3,a0,a1,a2,a3,b0,b1)                               \
    asm volatile(                                                             \
        "mma.sync.aligned.m16n8k8.row.col.f32.tf32.tf32.f32 "                 \
        "{%0,%1,%2,%3},{%4,%5,%6,%7},{%8,%9},{%0,%1,%2,%3};"                  \
        : "+f"(d0), "+f"(d1), "+f"(d2), "+f"(d3)                              \
        : "r"(a0), "r"(a1), "r"(a2), "r"(a3), "r"(b0), "r"(b1))

#define LDSM_X4(r0,r1,r2,r3,addr)                                              \
    asm volatile("ldmatrix.sync.aligned.m8n8.x4.b16 {%0,%1,%2,%3}, [%4];"      \
        : "=r"(r0), "=r"(r1), "=r"(r2), "=r"(r3) : "r"(addr))

#define CP_ASYNC16(dst, src)                                                   \
    asm volatile("cp.async.cg.shared.global [%0], [%1], 16;" :: "r"(dst), "l"(src))
#define CP_ASYNC16_Z(dst, src, sz)                                             \
    asm volatile("cp.async.cg.shared.global [%0], [%1], 16, %2;" :: "r"(dst), "l"(src), "r"(sz))

// smem: 3 stages x (A[128][36] + B[128][36]) floats
#define TILE_F   (128 * 36)
#define GEMM_SMEM_BYTES (3 * 2 * TILE_F * 4)   // 110592

// ---------------- TF32 tensor-core GEMM, cp.async 3-stage + ldmatrix ----------------
// C[M,N] = A[M,K] @ B[N,K]^T (+bias, +activation)
// ACT: 0 = none, 1 = softplus, 2 = exact gelu
// Block tile 128x128, K-tile 32, 256 threads = 8 warps (2m x 4n), warp tile 64x32.
// Fragment loads via ldmatrix.x4 (each 8x4-tf32 subtile viewed as 8x8-b16):
// thread l receives tf32 (row l/4, col l%4) of matrix l>>3 — identical mapping
// to the previous scalar-LDS version, so accumulation is bit-identical.
// Contract: M % 128 == 0, K % 64 == 0 (nIt >= 2), lda/ldb multiples of 4. N ragged OK.
template<int ACT>
__global__ void __launch_bounds__(256, 2)
tc_gemm_nt(const float* __restrict__ A, int lda,
           const float* __restrict__ Bm, int ldb,
           float* __restrict__ C, int ldc,
           int N, int K,
           const float* __restrict__ bias)
{
    extern __shared__ float sm[];
    float* const AsS[3] = { sm,          sm + 2 * TILE_F, sm + 4 * TILE_F };
    float* const BsS[3] = { sm + TILE_F, sm + 3 * TILE_F, sm + 5 * TILE_F };

    const int tid  = threadIdx.x;
    const int m0   = blockIdx.y * 128;
    const int n0   = blockIdx.x * 128;

    const int warp = tid >> 5;
    const int lane = tid & 31;
    const int wm   = (warp & 1) * 64;     // warp m-offset in block
    const int wn   = (warp >> 1) * 32;    // warp n-offset in block
    const int g    = lane >> 2;           // 0..7
    const int t    = lane & 3;            // 0..3

    const int crow = tid >> 3;            // copy row 0..31 (+32 per chunk)
    const int ckc  = (tid & 7) << 2;      // copy k-col 0,4,...,28

    // ldmatrix per-lane byte offsets (relative to tile base), constant across k
    // A, mf tile: rows (l&7) + 8*((l>>3)&1), k-col 4*(l>>4)
    int a_off[4];
#pragma unroll
    for (int mf = 0; mf < 4; mf++)
        a_off[mf] = ((wm + mf * 16 + (lane & 7) + 8 * ((lane >> 3) & 1)) * 36
                     + 4 * (lane >> 4)) * 4;
    // B, nf-pair p: n-rows (l&7) + 8*(l>>4), k-col 4*((l>>3)&1)
    int b_off[2];
#pragma unroll
    for (int p = 0; p < 2; p++)
        b_off[p] = ((wn + 16 * p + (lane & 7) + 8 * (lane >> 4)) * 36
                    + 4 * ((lane >> 3) & 1)) * 4;

    float acc[4][4][4];
#pragma unroll
    for (int i = 0; i < 4; i++)
#pragma unroll
        for (int j = 0; j < 4; j++)
#pragma unroll
            for (int c = 0; c < 4; c++) acc[i][j][c] = 0.f;

    const int nIt = K >> 5;

    auto load_tile = [&](int stage, int k0) {
        float* as = AsS[stage];
        float* bs = BsS[stage];
#pragma unroll
        for (int i = 0; i < 4; i++) {
            int row = crow + i * 32;
            uint32_t da = (uint32_t)__cvta_generic_to_shared(as + row * 36 + ckc);
            const float* ga = A + (size_t)(m0 + row) * lda + k0 + ckc;
            CP_ASYNC16(da, ga);

            int brow = n0 + row;
            uint32_t db = (uint32_t)__cvta_generic_to_shared(bs + row * 36 + ckc);
            const float* gb = Bm + (size_t)(brow < N ? brow : 0) * ldb + k0 + ckc;
            int sz = (brow < N) ? 16 : 0;
            CP_ASYNC16_Z(db, gb, sz);
        }
        asm volatile("cp.async.commit_group;");
    };

    load_tile(0, 0);
    load_tile(1, 32);

    for (int it = 0; it < nIt; ++it) {
        if (it + 2 < nIt) load_tile((it + 2) % 3, (it + 2) << 5);

        const int rem = nIt - 1 - it;
        if (rem >= 2)      asm volatile("cp.async.wait_group %0;" :: "n"(2));
        else if (rem == 1) asm volatile("cp.async.wait_group %0;" :: "n"(1));
        else               asm volatile("cp.async.wait_group %0;" :: "n"(0));
        __syncthreads();

        const uint32_t aBase = (uint32_t)__cvta_generic_to_shared(AsS[it % 3]);
        const uint32_t bBase = (uint32_t)__cvta_generic_to_shared(BsS[it % 3]);

#pragma unroll
        for (int ks = 0; ks < 4; ks++) {
            const int kB = ks * 8 * 4;    // k-step byte offset

            uint32_t a[4][4];
#pragma unroll
            for (int mf = 0; mf < 4; mf++)
                LDSM_X4(a[mf][0], a[mf][1], a[mf][2], a[mf][3],
                        aBase + a_off[mf] + kB);

            uint32_t b[4][2];
#pragma unroll
            for (int p = 0; p < 2; p++)
                LDSM_X4(b[2 * p][0], b[2 * p][1], b[2 * p + 1][0], b[2 * p + 1][1],
                        bBase + b_off[p] + kB);

#pragma unroll
            for (int mf = 0; mf < 4; mf++)
#pragma unroll
                for (int nf = 0; nf < 4; nf++)
                    MMA_TF32(acc[mf][nf][0], acc[mf][nf][1],
                             acc[mf][nf][2], acc[mf][nf][3],
                             a[mf][0], a[mf][1], a[mf][2], a[mf][3],
                             b[nf][0], b[nf][1]);
        }
        __syncthreads();
    }

    // ---- epilogue ----
#pragma unroll
    for (int nf = 0; nf < 4; nf++) {
        int col = n0 + wn + nf * 8 + t * 2;
        if (col >= N) continue;
        float bv0 = bias ? bias[col]     : 0.f;
        float bv1 = bias ? bias[col + 1] : 0.f;
#pragma unroll
        for (int mf = 0; mf < 4; mf++) {
            int row = m0 + wm + mf * 16 + g;
#pragma unroll
            for (int half = 0; half < 2; half++) {
                int r = row + half * 8;
                float v0 = acc[mf][nf][half * 2 + 0] + bv0;
                float v1 = acc[mf][nf][half * 2 + 1] + bv1;
                if (ACT == 1) {
                    v0 = fmaxf(v0, 0.f) + log1pf(expf(-fabsf(v0)));
                    v1 = fmaxf(v1, 0.f) + log1pf(expf(-fabsf(v1)));
                } else if (ACT == 2) {
                    v0 = 0.5f * v0 * (1.f + erff(v0 * 0.70710678118654752f));
                    v1 = 0.5f * v1 * (1.f + erff(v1 * 0.70710678118654752f));
                }
                *(float2*)(C + (size_t)r * ldc + col) = make_float2(v0, v1);
            }
        }
    }
}

// ---------------- causal depthwise conv (K=4) + bias + SiLU ----------------
__global__ void conv_silu_kernel(const float* __restrict__ conv_w,
                                 const float* __restrict__ conv_b)
{
    int idx = blockIdx.x * blockDim.x + threadIdx.x;
    if (idx >= BL * DI) return;
    int d  = idx % DI;
    int bl = idx / DI;
    int l  = bl % L_;

    float acc = conv_b[d];
#pragma unroll
    for (int j = 0; j < 4; j++) {
        int ls = l - 3 + j;
        if (ls >= 0)
            acc += g_xz[(size_t)(bl - (3 - j)) * (2 * DI) + d] * conv_w[d * 4 + j];
    }
    g_xc[idx] = acc / (1.f + __expf(-acc));     // silu
}

// ---------------- selective scan (unroll-8 prefetch) ----------------
__global__ void scan_kernel(const float* __restrict__ A_log,
                            const float* __restrict__ Dp)
{
    const int tid = threadIdx.x;
    const int s   = tid & 15;
    const int cg  = blockIdx.x * 16 + (tid >> 4);   // 0..B_*DI-1
    const int b   = cg / DI;
    const int d   = cg % DI;

    const float a  = -expf(A_log[d * DS + s]);
    const float Dd = Dp[d];

    const float* p_dt = g_dt   + (size_t)b * L_ * DI + d;
    const float* p_x  = g_xc   + (size_t)b * L_ * DI + d;
    const float* p_z  = g_xz   + (size_t)b * L_ * (2 * DI) + DI + d;
    const float* p_B  = g_xdbl + (size_t)b * L_ * XPN + DTR + s;
    const float* p_C  = p_B + DS;
    float*       p_y  = g_y    + (size_t)b * L_ * DI + d;

    float h = 0.f;
    for (int l0 = 0; l0 < L_; l0 += 8) {
        float dtv[8], xv[8], Bv[8], Cv[8], zv[8];
#pragma unroll
        for (int u = 0; u < 8; u++) {
            int l = l0 + u;
            dtv[u] = p_dt[(size_t)l * DI];
            xv[u]  = p_x [(size_t)l * DI];
            zv[u]  = p_z [(size_t)l * 2 * DI];
            Bv[u]  = p_B [l * XPN];
            Cv[u]  = p_C [l * XPN];
        }
#pragma unroll
        for (int u = 0; u < 8; u++) {
            h = __expf(dtv[u] * a) * h + dtv[u] * Bv[u] * xv[u];

            float p = h * Cv[u];
            p += __shfl_xor_sync(0xffffffffu, p, 8);
            p += __shfl_xor_sync(0xffffffffu, p, 4);
            p += __shfl_xor_sync(0xffffffffu, p, 2);
            p += __shfl_xor_sync(0xffffffffu, p, 1);

            if (s == 0) {
                float yv = p + xv[u] * Dd;
                p_y[(size_t)(l0 + u) * DI] = yv * (zv[u] / (1.f + __expf(-zv[u])));
            }
        }
    }
}

// ---------------- fused residual add + RMSNorm ----------------
__global__ void rmsnorm_kernel(const float* __restrict__ x,
                               const float* __restrict__ res,
                               const float* __restrict__ w,
                               float* __restrict__ out)
{
    const int row = blockIdx.x;
    const int tid = threadIdx.x;

    float4 xv = ((const float4*)(x   + (size_t)row * DM))[tid];
    float4 rv = ((const float4*)(res + (size_t)row * DM))[tid];
    float v0 = xv.x + rv.x, v1 = xv.y + rv.y, v2 = xv.z + rv.z, v3 = xv.w + rv.w;

    float ss = v0 * v0 + v1 * v1 + v2 * v2 + v3 * v3;
#pragma unroll
    for (int m = 16; m; m >>= 1) ss += __shfl_xor_sync(0xffffffffu, ss, m);

    __shared__ float red[8];
    if ((tid & 31) == 0) red[tid >> 5] = ss;
    __syncthreads();
    if (tid < 8) {
        float tt = red[tid];
#pragma unroll
        for (int m = 4; m; m >>= 1) tt += __shfl_xor_sync(0xffu, tt, m);
        if (tid == 0) red[0] = tt;
    }
    __syncthreads();

    const float scale = rsqrtf(red[0] / (float)DM + 1e-6f);
    float4 wv = ((const float4*)w)[tid];
    float4 o;
    o.x = v0 * scale * wv.x; o.y = v1 * scale * wv.y;
    o.z = v2 * scale * wv.z; o.w = v3 * scale * wv.w;
    ((float4*)(out + (size_t)row * DM))[tid] = o;
}

// ---------------- launch ----------------
extern "C" void kernel_launch(void* const* d_in, const int* in_sizes, int n_in,
                              void* d_out, int out_size)
{
    const float* Z       = (const float*)d_in[0];
    const float* in_w    = (const float*)d_in[1];   // (2*DI, DM)
    const float* conv_w  = (const float*)d_in[2];   // (DI, 4)
    const float* conv_b  = (const float*)d_in[3];   // (DI,)
    const float* xproj_w = (const float*)d_in[4];   // (96, DI)
    const float* dtp_w   = (const float*)d_in[5];   // (DI, 64)
    const float* dtp_b   = (const float*)d_in[6];   // (DI,)
    const float* A_log   = (const float*)d_in[7];   // (DI, DS)
    const float* Dp      = (const float*)d_in[8];   // (DI,)
    const float* outp_w  = (const float*)d_in[9];   // (DM, DI)
    const float* w1      = (const float*)d_in[10];  // (DFF, DM)
    const float* b1      = (const float*)d_in[11];
    const float* w2      = (const float*)d_in[12];  // (DM, DFF)
    const float* b2      = (const float*)d_in[13];
    const float* nw      = (const float*)d_in[14];  // (DM,)
    float* out = (float*)d_out;

    float *xz, *xc, *xdbl, *dtb, *yb, *mam, *zm, *hb, *mlp;
    cudaGetSymbolAddress((void**)&xz,   g_xz);
    cudaGetSymbolAddress((void**)&xc,   g_xc);
    cudaGetSymbolAddress((void**)&xdbl, g_xdbl);
    cudaGetSymbolAddress((void**)&dtb,  g_dt);
    cudaGetSymbolAddress((void**)&yb,   g_y);
    cudaGetSymbolAddress((void**)&mam,  g_mam);
    cudaGetSymbolAddress((void**)&zm,   g_zm);
    cudaGetSymbolAddress((void**)&hb,   g_h);
    cudaGetSymbolAddress((void**)&mlp,  g_mlp);

    cudaFuncSetAttribute(tc_gemm_nt<0>, cudaFuncAttributeMaxDynamicSharedMemorySize, GEMM_SMEM_BYTES);
    cudaFuncSetAttribute(tc_gemm_nt<1>, cudaFuncAttributeMaxDynamicSharedMemorySize, GEMM_SMEM_BYTES);
    cudaFuncSetAttribute(tc_gemm_nt<2>, cudaFuncAttributeMaxDynamicSharedMemorySize, GEMM_SMEM_BYTES);

    const dim3 thr(256);
    const int  SB = GEMM_SMEM_BYTES;

    // 1) xz = Z @ in_proj_w^T            (2048 x 4096, K=1024)
    tc_gemm_nt<0><<<dim3(4096 / 128, BL / 128), thr, SB>>>(Z, DM, in_w, DM, xz, 2 * DI, 2 * DI, DM, nullptr);

    // 2) x = silu(causal_dwconv(x) + b)
    conv_silu_kernel<<<(BL * DI + 255) / 256, thr>>>(conv_w, conv_b);

    // 3) x_dbl = x @ x_proj_w^T          (2048 x 96, K=2048)
    tc_gemm_nt<0><<<dim3(1, BL / 128), thr, SB>>>(xc, DI, xproj_w, DI, xdbl, XPN, XPN, DI, nullptr);

    // 4) dt = softplus(dt_part @ dt_proj_w^T + dt_b)   (2048 x 2048, K=64; A lda=96)
    tc_gemm_nt<1><<<dim3(DI / 128, BL / 128), thr, SB>>>(xdbl, XPN, dtp_w, DTR, dtb, DI, DI, DTR, dtp_b);

    // 5) selective scan (fused gating)
    scan_kernel<<<(B_ * DI) / 16, thr>>>(A_log, Dp);

    // 6) mamba_out = y @ out_proj_w^T    (2048 x 1024, K=2048)
    tc_gemm_nt<0><<<dim3(DM / 128, BL / 128), thr, SB>>>(yb, DI, outp_w, DI, mam, DM, DM, DI, nullptr);

    // 7) Z_mam = rmsnorm(mamba_out + Z)
    rmsnorm_kernel<<<BL, thr>>>(mam, Z, nw, zm);

    // 8) h = gelu(Z_mam @ w1^T + b1)     (2048 x 4096, K=1024)
    tc_gemm_nt<2><<<dim3(DFF / 128, BL / 128), thr, SB>>>(zm, DM, w1, DM, hb, DFF, DFF, DM, b1);

    // 9) mlp = h @ w2^T + b2             (2048 x 1024, K=4096)
    tc_gemm_nt<0><<<dim3(DM / 128, BL / 128), thr, SB>>>(hb, DFF, w2, DFF, mlp, DM, DM, DFF, b2);

    // 10) out = rmsnorm(mlp + Z_mam)
    rmsnorm_kernel<<<BL, thr>>>(mlp, zm, nw, out);
}